// round 5
// baseline (speedup 1.0000x reference)
#include <cuda_runtime.h>
#include <cuda_bf16.h>

#define NBLOCKS  1184
#define NTHREADS 256
#define TILE     256
#define EPS      0.0001f

__device__ double       g_partials[NBLOCKS];
__device__ unsigned int g_counter = 0;

// Per-row loss. z = clamp((x-u)/s, -3, 3) is the exact simplification of
// sqrt2*erfinv(2*clip(ndtr(t),eps,1-eps)-1) clipped to [-3,3], since
// Phi^-1(eps) = -3.719 < -3 (the eps clip never binds inside [-3,3]).
// nll = 0.5*t^2 + log(s) = 0.5*t^2 + param  (s = exp(param)).
__device__ __forceinline__ float row_loss(
    float ra, float rb,
    float pu1, float ps1, float pu2, float ps2, float pu3, float ps3,
    float r12, float r13, float r23,
    float revert, float Rtop, float Top, float Close)
{
    float u1 = __expf(pu1), s1 = __expf(ps1);
    float u2 = __expf(pu2), s2 = __expf(ps2);
    float u3 = __expf(pu3), s3 = __expf(ps3);

    float t1 = (Rtop  - u1) * __fdividef(1.0f, fmaxf(s1, EPS));
    float t2 = (Top   - u2) * __fdividef(1.0f, fmaxf(s2, EPS));
    float t3 = (Close - u3) * __fdividef(1.0f, fmaxf(s3, EPS));
    float z1 = fminf(fmaxf(t1, -3.0f), 3.0f);
    float z2 = fminf(fmaxf(t2, -3.0f), 3.0f);
    float z3 = fminf(fmaxf(t3, -3.0f), 3.0f);

    float nll_sum = 0.5f * (t1 * t1 + t2 * t2 + t3 * t3) + (ps1 + ps2 + ps3);

    float detR = 1.0f + 2.0f * r12 * r13 * r23
               - r12 * r12 - r13 * r13 - r23 * r23;
    float inv_det = 1.0f / detR;
    float i00 = (1.0f - r23 * r23) * inv_det;
    float i01 = (r13 * r23 - r12) * inv_det;
    float i02 = (r12 * r23 - r13) * inv_det;
    float i11 = (1.0f - r13 * r13) * inv_det;
    float i12 = (r12 * r13 - r23) * inv_det;
    float i22 = (1.0f - r12 * r12) * inv_det;

    float exp_term = 0.5f * ((i00 - 1.0f) * z1 * z1
                           + (i11 - 1.0f) * z2 * z2
                           + (i22 - 1.0f) * z3 * z3)
                   + (i01 * z1 * z2 + i02 * z1 * z3 + i12 * z2 * z3);

    float c_gauss = 0.5f * __logf(fmaxf(detR, EPS)) + exp_term;
    float copula  = revert * (c_gauss + nll_sum);

    float m   = fmaxf(ra, rb);
    float lse = m + __logf(1.0f + __expf(-fabsf(ra - rb)));
    float sel = (revert != 0.0f) ? rb : ra;
    return (lse - sel) + copula;
}

__global__ __launch_bounds__(NTHREADS, 8)
void gausscop_fused(const float* __restrict__ pred_r,
                    const float* __restrict__ pred_params,
                    const float* __restrict__ pred_corr,
                    const float* __restrict__ y_true,
                    float* __restrict__ out,
                    int n)
{
    // Staged arrays: the two whose direct per-row loads waste L1tex wavefronts.
    __shared__ float s_p[TILE * 6];   // 1536 floats = 384 float4 (6 KB)
    __shared__ float s_c[TILE * 3];   // 768 floats  = 192 float4 (3 KB)

    const int ntiles = (n + TILE - 1) / TILE;
    const int tid = threadIdx.x;
    float acc = 0.0f;

    for (int t = blockIdx.x; t < ntiles; t += gridDim.x) {
        const int base = t * TILE;
        const int rows = min(TILE, n - base);

        if (rows == TILE) {
            // Cooperative float4 staging: one L1tex wavefront per 128B line.
            const float4* gp = (const float4*)(pred_params + 6L * base); // 384 f4
            const float4* gc = (const float4*)(pred_corr   + 3L * base); // 192 f4
            float4* sp = (float4*)s_p;
            float4* sc = (float4*)s_c;
            sp[tid] = gp[tid];                                 // 0..255
            if (tid < 128) sp[256 + tid] = gp[256 + tid];      // 256..383
            if (tid < 192) sc[tid] = gc[tid];                  // 0..191
        } else {
            // tail tile: guarded scalar staging
            for (int k = tid; k < rows * 6; k += NTHREADS)
                s_p[k] = pred_params[6L * base + k];
            for (int k = tid; k < rows * 3; k += NTHREADS)
                s_c[k] = pred_corr[3L * base + k];
        }
        __syncthreads();

        if (tid < rows) {
            const long i = base + tid;
            // direct loads: already wavefront-optimal strides (8B / 16B)
            float2 rr = *(const float2*)(pred_r + 2 * i);
            float4 y  = *(const float4*)(y_true + 4 * i);
            // smem reads
            const float2* prow = (const float2*)(s_p + 6 * tid);
            float2 p01 = prow[0], p23 = prow[1], p45 = prow[2];
            const float* crow = s_c + 3 * tid;
            float c0 = crow[0], c1 = crow[1], c2 = crow[2];

            acc += row_loss(rr.x, rr.y,
                            p01.x, p01.y, p23.x, p23.y, p45.x, p45.y,
                            c0, c1, c2,
                            y.x, y.y, y.z, y.w);
        }
        __syncthreads();
    }

    // ---- intra-block reduce ----
    #pragma unroll
    for (int o = 16; o; o >>= 1)
        acc += __shfl_xor_sync(0xFFFFFFFFu, acc, o);

    __shared__ float warpsums[NTHREADS / 32];
    __shared__ bool  amLast;
    int lane = threadIdx.x & 31;
    int wid  = threadIdx.x >> 5;
    if (lane == 0) warpsums[wid] = acc;
    __syncthreads();

    if (threadIdx.x == 0) {
        double bs = 0.0;
        #pragma unroll
        for (int w = 0; w < NTHREADS / 32; w++) bs += (double)warpsums[w];
        g_partials[blockIdx.x] = bs;
        __threadfence();
        unsigned int tk = atomicAdd(&g_counter, 1u);
        amLast = (tk == gridDim.x - 1);
    }
    __syncthreads();

    // ---- last block: deterministic final reduction ----
    if (amLast) {
        __shared__ double sh[NTHREADS];
        double s = 0.0;
        volatile double* gpp = g_partials;
        for (int k = threadIdx.x; k < NBLOCKS; k += NTHREADS) s += gpp[k];
        sh[threadIdx.x] = s;
        __syncthreads();
        for (int st = NTHREADS / 2; st > 0; st >>= 1) {
            if (threadIdx.x < st) sh[threadIdx.x] += sh[threadIdx.x + st];
            __syncthreads();
        }
        if (threadIdx.x == 0) {
            out[0] = (float)(sh[0] / (double)n);
            g_counter = 0;   // reset for next graph replay
        }
    }
}

extern "C" void kernel_launch(void* const* d_in, const int* in_sizes, int n_in,
                              void* d_out, int out_size)
{
    const float* pred_r      = (const float*)d_in[0];
    const float* pred_params = (const float*)d_in[1];
    const float* pred_corr   = (const float*)d_in[2];
    const float* y_true      = (const float*)d_in[3];
    int n = in_sizes[0] / 2;   // pred_r is (B, 2)

    gausscop_fused<<<NBLOCKS, NTHREADS>>>(pred_r, pred_params, pred_corr,
                                          y_true, (float*)d_out, n);
}

// round 6
// speedup vs baseline: 1.1616x; 1.1616x over previous
#include <cuda_runtime.h>
#include <cstdint>

#define NBLOCKS  296
#define NTHREADS 256
#define TILE     256
#define STAGES   3
#define EPS      0.0001f

__device__ double       g_partials[NBLOCKS];
__device__ unsigned int g_counter = 0;

// z = clamp((x-u)/s, -3, 3) is the exact simplification of
// sqrt2*erfinv(2*clip(ndtr(t),eps,1-eps)-1) clipped to [-3,3]
// (Phi^-1(eps) = -3.719 < -3, so the eps clip never binds in [-3,3]).
// nll = 0.5*t^2 + log(s) = 0.5*t^2 + param  (s = exp(param)).
__device__ __forceinline__ float row_loss(
    float ra, float rb,
    float pu1, float ps1, float pu2, float ps2, float pu3, float ps3,
    float r12, float r13, float r23,
    float revert, float Rtop, float Top, float Close)
{
    float u1 = __expf(pu1), s1 = __expf(ps1);
    float u2 = __expf(pu2), s2 = __expf(ps2);
    float u3 = __expf(pu3), s3 = __expf(ps3);

    float t1 = (Rtop  - u1) * __fdividef(1.0f, fmaxf(s1, EPS));
    float t2 = (Top   - u2) * __fdividef(1.0f, fmaxf(s2, EPS));
    float t3 = (Close - u3) * __fdividef(1.0f, fmaxf(s3, EPS));
    float z1 = fminf(fmaxf(t1, -3.0f), 3.0f);
    float z2 = fminf(fmaxf(t2, -3.0f), 3.0f);
    float z3 = fminf(fmaxf(t3, -3.0f), 3.0f);

    float nll_sum = 0.5f * (t1 * t1 + t2 * t2 + t3 * t3) + (ps1 + ps2 + ps3);

    float detR = 1.0f + 2.0f * r12 * r13 * r23
               - r12 * r12 - r13 * r13 - r23 * r23;
    float inv_det = 1.0f / detR;
    float i00 = (1.0f - r23 * r23) * inv_det;
    float i01 = (r13 * r23 - r12) * inv_det;
    float i02 = (r12 * r23 - r13) * inv_det;
    float i11 = (1.0f - r13 * r13) * inv_det;
    float i12 = (r12 * r13 - r23) * inv_det;
    float i22 = (1.0f - r12 * r12) * inv_det;

    float exp_term = 0.5f * ((i00 - 1.0f) * z1 * z1
                           + (i11 - 1.0f) * z2 * z2
                           + (i22 - 1.0f) * z3 * z3)
                   + (i01 * z1 * z2 + i02 * z1 * z3 + i12 * z2 * z3);

    float c_gauss = 0.5f * __logf(fmaxf(detR, EPS)) + exp_term;
    float copula  = revert * (c_gauss + nll_sum);

    float m   = fmaxf(ra, rb);
    float lse = m + __logf(1.0f + __expf(-fabsf(ra - rb)));
    float sel = (revert != 0.0f) ? rb : ra;
    return (lse - sel) + copula;
}

__device__ __forceinline__ uint32_t smem_u32(const void* p) {
    return (uint32_t)__cvta_generic_to_shared(p);
}

__device__ __forceinline__ void mbar_init(uint32_t mbar, uint32_t cnt) {
    asm volatile("mbarrier.init.shared.b64 [%0], %1;" :: "r"(mbar), "r"(cnt) : "memory");
}
__device__ __forceinline__ void mbar_expect_tx(uint32_t mbar, uint32_t bytes) {
    asm volatile("mbarrier.arrive.expect_tx.shared.b64 _, [%0], %1;"
                 :: "r"(mbar), "r"(bytes) : "memory");
}
__device__ __forceinline__ void bulk_g2s(uint32_t dst, const void* src,
                                         uint32_t bytes, uint32_t mbar) {
    asm volatile(
        "cp.async.bulk.shared::cta.global.mbarrier::complete_tx::bytes "
        "[%0], [%1], %2, [%3];"
        :: "r"(dst), "l"(src), "r"(bytes), "r"(mbar) : "memory");
}
__device__ __forceinline__ void mbar_wait(uint32_t mbar, uint32_t parity) {
    uint32_t done;
    asm volatile(
        "{\n\t.reg .pred p;\n\t"
        "mbarrier.try_wait.parity.acquire.cta.shared::cta.b64 p, [%1], %2;\n\t"
        "selp.b32 %0, 1, 0, p;\n\t}"
        : "=r"(done) : "r"(mbar), "r"(parity) : "memory");
    if (!done) {
        asm volatile(
            "{\n\t.reg .pred P1;\n\t"
            "WL_%=:\n\t"
            "mbarrier.try_wait.parity.acquire.cta.shared::cta.b64 P1, [%0], %1, 0x989680;\n\t"
            "@P1 bra.uni WD_%=;\n\t"
            "bra.uni WL_%=;\n\t"
            "WD_%=:\n\t}"
            :: "r"(mbar), "r"(parity) : "memory");
    }
}

__global__ __launch_bounds__(NTHREADS, 2)
void gausscop_tma(const float* __restrict__ pred_r,
                  const float* __restrict__ pred_params,
                  const float* __restrict__ pred_corr,
                  const float* __restrict__ y_true,
                  float* __restrict__ out,
                  int n)
{
    __shared__ alignas(128) float s_r[STAGES][TILE * 2];  //  2 KB/stage
    __shared__ alignas(128) float s_p[STAGES][TILE * 6];  //  6 KB/stage
    __shared__ alignas(128) float s_c[STAGES][TILE * 3];  //  3 KB/stage
    __shared__ alignas(128) float s_y[STAGES][TILE * 4];  //  4 KB/stage
    __shared__ alignas(8)  uint64_t mbar_store[STAGES];

    const int tid = threadIdx.x;
    const uint32_t mb0 = smem_u32(&mbar_store[0]);

    if (tid == 0) {
        #pragma unroll
        for (int s = 0; s < STAGES; s++) mbar_init(mb0 + 8u * s, 1);
    }
    __syncthreads();

    const int ntiles = n / TILE;          // full tiles only
    // local tile j -> global tile (blockIdx.x + j*gridDim.x)
    int nlocal = 0;
    if ((int)blockIdx.x < ntiles)
        nlocal = (ntiles - blockIdx.x + gridDim.x - 1) / gridDim.x;

    const uint32_t TILE_BYTES = TILE * 60u;   // 8+24+12+16 bytes per row

    // producer: thread 0 issues 4 bulk copies for local tile j into slot j%STAGES
    auto issue = [&](int j) {
        if (tid == 0) {
            long gt = (long)blockIdx.x + (long)j * gridDim.x; // global tile
            int  slot = j % STAGES;
            uint32_t mb = mb0 + 8u * slot;
            mbar_expect_tx(mb, TILE_BYTES);
            long base = gt * TILE;
            bulk_g2s(smem_u32(s_r[slot]), pred_r      + 2 * base, TILE * 8,  mb);
            bulk_g2s(smem_u32(s_p[slot]), pred_params + 6 * base, TILE * 24, mb);
            bulk_g2s(smem_u32(s_c[slot]), pred_corr   + 3 * base, TILE * 12, mb);
            bulk_g2s(smem_u32(s_y[slot]), y_true      + 4 * base, TILE * 16, mb);
        }
    };

    // prologue: fill the ring
    const int pro = nlocal < STAGES ? nlocal : STAGES;
    for (int j = 0; j < pro; j++) issue(j);

    float acc = 0.0f;
    for (int j = 0; j < nlocal; j++) {
        const int slot   = j % STAGES;
        const uint32_t parity = (uint32_t)((j / STAGES) & 1);
        mbar_wait(mb0 + 8u * slot, parity);

        // one row per thread from smem
        const float2* rr2 = (const float2*)(s_r[slot] + 2 * tid);
        float2 rr = rr2[0];
        const float2* pp2 = (const float2*)(s_p[slot] + 6 * tid);
        float2 p01 = pp2[0], p23 = pp2[1], p45 = pp2[2];
        const float* cc = s_c[slot] + 3 * tid;
        float c0 = cc[0], c1 = cc[1], c2 = cc[2];
        const float4* yy4 = (const float4*)(s_y[slot] + 4 * tid);
        float4 y = yy4[0];

        acc += row_loss(rr.x, rr.y,
                        p01.x, p01.y, p23.x, p23.y, p45.x, p45.y,
                        c0, c1, c2,
                        y.x, y.y, y.z, y.w);

        __syncthreads();              // all consumers done with this slot
        if (j + STAGES < nlocal) issue(j + STAGES);
    }

    // tail rows (n % TILE): direct loads, block 0 only (tiny)
    if (blockIdx.x == 0) {
        for (int i = ntiles * TILE + tid; i < n; i += NTHREADS) {
            long li = i;
            float2 rr  = *(const float2*)(pred_r      + 2 * li);
            float2 p01 = *(const float2*)(pred_params + 6 * li);
            float2 p23 = *(const float2*)(pred_params + 6 * li + 2);
            float2 p45 = *(const float2*)(pred_params + 6 * li + 4);
            const float* pc = pred_corr + 3 * li;
            float4 y   = *(const float4*)(y_true + 4 * li);
            acc += row_loss(rr.x, rr.y,
                            p01.x, p01.y, p23.x, p23.y, p45.x, p45.y,
                            pc[0], pc[1], pc[2],
                            y.x, y.y, y.z, y.w);
        }
    }

    // ---- intra-block reduce ----
    #pragma unroll
    for (int o = 16; o; o >>= 1)
        acc += __shfl_xor_sync(0xFFFFFFFFu, acc, o);

    __shared__ float warpsums[NTHREADS / 32];
    __shared__ bool  amLast;
    int lane = tid & 31;
    int wid  = tid >> 5;
    if (lane == 0) warpsums[wid] = acc;
    __syncthreads();

    if (tid == 0) {
        double bs = 0.0;
        #pragma unroll
        for (int w = 0; w < NTHREADS / 32; w++) bs += (double)warpsums[w];
        g_partials[blockIdx.x] = bs;
        __threadfence();
        unsigned int tk = atomicAdd(&g_counter, 1u);
        amLast = (tk == gridDim.x - 1);
    }
    __syncthreads();

    // ---- last block: deterministic final reduction ----
    if (amLast) {
        __shared__ double sh[NTHREADS];
        double s = 0.0;
        volatile double* gpp = g_partials;
        for (int k = tid; k < NBLOCKS; k += NTHREADS) s += gpp[k];
        sh[tid] = s;
        __syncthreads();
        for (int st = NTHREADS / 2; st > 0; st >>= 1) {
            if (tid < st) sh[tid] += sh[tid + st];
            __syncthreads();
        }
        if (tid == 0) {
            out[0] = (float)(sh[0] / (double)n);
            g_counter = 0;   // reset for next graph replay
        }
    }
}

extern "C" void kernel_launch(void* const* d_in, const int* in_sizes, int n_in,
                              void* d_out, int out_size)
{
    const float* pred_r      = (const float*)d_in[0];
    const float* pred_params = (const float*)d_in[1];
    const float* pred_corr   = (const float*)d_in[2];
    const float* y_true      = (const float*)d_in[3];
    int n = in_sizes[0] / 2;   // pred_r is (B, 2)

    gausscop_tma<<<NBLOCKS, NTHREADS>>>(pred_r, pred_params, pred_corr,
                                        y_true, (float*)d_out, n);
}